// round 2
// baseline (speedup 1.0000x reference)
#include <cuda_runtime.h>

#define BATCH 8
#define KLEN  8192
#define HDIM  512
#define TK    16                        // rows per tile (one warp per row)
#define TILES_PER_BATCH (KLEN / TK)     // 512
#define NBLOCKS (BATCH * TILES_PER_BATCH) // 4096
#define EPSV  1e-8f
#define FULL  0xffffffffu

// Decoupled-lookback state (allocation-free: __device__ globals).
// bid = tile*8 + batch  (batch-interleaved so the 8 chains progress together)
__device__ volatile int g_flag[NBLOCKS];  // 0=invalid, 1=aggregate ready, 2=inclusive ready
__device__ float2 g_agg[NBLOCKS];
__device__ float2 g_inc[NBLOCKS];

__global__ void init_kernel() {
    int i = blockIdx.x * blockDim.x + threadIdx.x;
    if (i < NBLOCKS) g_flag[i] = 0;
}

__global__ __launch_bounds__(512, 1) void clnorm_kernel(const float* __restrict__ x,
                                                        const float* __restrict__ gamma,
                                                        const float* __restrict__ beta,
                                                        float* __restrict__ out) {
    __shared__ float sWs[TK], sWq[TK];     // per-row (per-warp) sums
    __shared__ float sIncS[TK], sIncQ[TK]; // intra-tile inclusive scan
    __shared__ float sExcl[2];             // tile exclusive prefix (from lookback)

    const int bid   = blockIdx.x;
    const int batch = bid & 7;
    const int tile  = bid >> 3;            // tile index within batch
    const int w     = threadIdx.x >> 5;    // warp == row within tile
    const int lane  = threadIdx.x & 31;

    const int k = tile * TK + w;           // time step within batch
    const size_t row = (size_t)batch * KLEN + k;

    // ---- load row into registers (4x LDG.128 per lane, independent) ----
    const float4* px = reinterpret_cast<const float4*>(x) + row * (HDIM / 4);
    float4 v0 = px[lane];
    float4 v1 = px[lane + 32];
    float4 v2 = px[lane + 64];
    float4 v3 = px[lane + 96];

    // ---- per-row sum / sqsum, xor-reduce so every lane holds the result ----
    float s = (v0.x + v0.y + v0.z + v0.w) + (v1.x + v1.y + v1.z + v1.w)
            + (v2.x + v2.y + v2.z + v2.w) + (v3.x + v3.y + v3.z + v3.w);
    float q = (v0.x*v0.x + v0.y*v0.y + v0.z*v0.z + v0.w*v0.w)
            + (v1.x*v1.x + v1.y*v1.y + v1.z*v1.z + v1.w*v1.w)
            + (v2.x*v2.x + v2.y*v2.y + v2.z*v2.z + v2.w*v2.w)
            + (v3.x*v3.x + v3.y*v3.y + v3.z*v3.z + v3.w*v3.w);
#pragma unroll
    for (int o = 16; o; o >>= 1) {
        s += __shfl_xor_sync(FULL, s, o);
        q += __shfl_xor_sync(FULL, q, o);
    }
    if (lane == 0) { sWs[w] = s; sWq[w] = q; }
    __syncthreads();

    // ---- warp 0: intra-tile scan, publish aggregate, decoupled lookback ----
    if (w == 0) {
        float ts = (lane < TK) ? sWs[lane] : 0.f;
        float tq = (lane < TK) ? sWq[lane] : 0.f;
#pragma unroll
        for (int o = 1; o < 32; o <<= 1) {
            float a = __shfl_up_sync(FULL, ts, o);
            float c = __shfl_up_sync(FULL, tq, o);
            if (lane >= o) { ts += a; tq += c; }
        }
        if (lane < TK) { sIncS[lane] = ts; sIncQ[lane] = tq; }
        float aggS = __shfl_sync(FULL, ts, 31);   // tile total (padding lanes add 0)
        float aggQ = __shfl_sync(FULL, tq, 31);

        // publish aggregate (or inclusive, for the first tile of each chain)
        if (lane == 0) {
            if (tile == 0) {
                g_inc[bid] = make_float2(aggS, aggQ);
                __threadfence();
                g_flag[bid] = 2;
            } else {
                g_agg[bid] = make_float2(aggS, aggQ);
                __threadfence();
                g_flag[bid] = 1;
            }
        }

        float exS = 0.f, exQ = 0.f;
        if (tile > 0) {
            int cur = bid;
            for (;;) {
                int win = cur >> 3; if (win > 32) win = 32;  // #predecessors in window
                int p = cur - 8 * (lane + 1);                // lane 0 = nearest predecessor
                int f = 2;
                float vS = 0.f, vQ = 0.f;
                if (lane < win) {
                    do { f = g_flag[p]; } while (f == 0);
                    __threadfence();
                    float2 t = (f == 2) ? g_inc[p] : g_agg[p];
                    vS = t.x; vQ = t.y;
                }
                unsigned m = __ballot_sync(FULL, (lane < win) && (f == 2));
                if (m) {
                    int L = __ffs(m) - 1;                    // nearest inclusive prefix
                    float cS = (lane <= L) ? vS : 0.f;
                    float cQ = (lane <= L) ? vQ : 0.f;
#pragma unroll
                    for (int o = 16; o; o >>= 1) {
                        cS += __shfl_xor_sync(FULL, cS, o);
                        cQ += __shfl_xor_sync(FULL, cQ, o);
                    }
                    exS += cS; exQ += cQ;
                    break;
                } else {
                    float cS = (lane < win) ? vS : 0.f;      // all aggregates
                    float cQ = (lane < win) ? vQ : 0.f;
#pragma unroll
                    for (int o = 16; o; o >>= 1) {
                        cS += __shfl_xor_sync(FULL, cS, o);
                        cQ += __shfl_xor_sync(FULL, cQ, o);
                    }
                    exS += cS; exQ += cQ;
                    cur -= 8 * win;
                }
            }
            if (lane == 0) {
                g_inc[bid] = make_float2(exS + aggS, exQ + aggQ);
                __threadfence();
                g_flag[bid] = 2;
            }
        }
        if (lane == 0) { sExcl[0] = exS; sExcl[1] = exQ; }
    }
    __syncthreads();

    // ---- per-row moments: tile exclusive + intra-tile exclusive + own row ----
    float exclS = sExcl[0] + (w ? sIncS[w - 1] : 0.f);
    float exclQ = sExcl[1] + (w ? sIncQ[w - 1] : 0.f);
    float cs = exclS + s;
    float cq = exclQ + q;
    float cnt = (float)((k + 1) * HDIM);     // exact in fp32 (<= 2^22)
    float mean = cs / cnt;
    float var  = cq / cnt - mean * mean;
    float inv  = rsqrtf(var + EPSV);

    // ---- normalize register-resident tile and store ----
    const float4* pg = reinterpret_cast<const float4*>(gamma);
    const float4* pb = reinterpret_cast<const float4*>(beta);
    float4* po = reinterpret_cast<float4*>(out) + row * (HDIM / 4);

    float4 g0 = pg[lane],      b0 = pb[lane];
    float4 g1 = pg[lane + 32], b1 = pb[lane + 32];
    float4 g2 = pg[lane + 64], b2 = pb[lane + 64];
    float4 g3 = pg[lane + 96], b3 = pb[lane + 96];

    float4 o0, o1, o2, o3;
    o0.x = g0.x * (v0.x - mean) * inv + b0.x;
    o0.y = g0.y * (v0.y - mean) * inv + b0.y;
    o0.z = g0.z * (v0.z - mean) * inv + b0.z;
    o0.w = g0.w * (v0.w - mean) * inv + b0.w;
    o1.x = g1.x * (v1.x - mean) * inv + b1.x;
    o1.y = g1.y * (v1.y - mean) * inv + b1.y;
    o1.z = g1.z * (v1.z - mean) * inv + b1.z;
    o1.w = g1.w * (v1.w - mean) * inv + b1.w;
    o2.x = g2.x * (v2.x - mean) * inv + b2.x;
    o2.y = g2.y * (v2.y - mean) * inv + b2.y;
    o2.z = g2.z * (v2.z - mean) * inv + b2.z;
    o2.w = g2.w * (v2.w - mean) * inv + b2.w;
    o3.x = g3.x * (v3.x - mean) * inv + b3.x;
    o3.y = g3.y * (v3.y - mean) * inv + b3.y;
    o3.z = g3.z * (v3.z - mean) * inv + b3.z;
    o3.w = g3.w * (v3.w - mean) * inv + b3.w;

    po[lane]      = o0;
    po[lane + 32] = o1;
    po[lane + 64] = o2;
    po[lane + 96] = o3;
}

extern "C" void kernel_launch(void* const* d_in, const int* in_sizes, int n_in,
                              void* d_out, int out_size) {
    const float* x     = (const float*)d_in[0];
    const float* gamma = (const float*)d_in[1];
    const float* beta  = (const float*)d_in[2];
    float* out         = (float*)d_out;

    init_kernel<<<NBLOCKS / 1024, 1024>>>();
    clnorm_kernel<<<NBLOCKS, 512>>>(x, gamma, beta, out);
}